// round 11
// baseline (speedup 1.0000x reference)
#include <cuda_runtime.h>
#include <cuda_bf16.h>
#include <math.h>
#include <stdint.h>

#define D_MODEL 2048
#define N_HEAD  16
#define HEAD_DIM 128
#define BATCH   2
#define SEQ     2048

// ---------------------------------------------------------------------------
// Static scratch (no cudaMalloc anywhere)
// ---------------------------------------------------------------------------
static __device__ float g_rope[(size_t)SEQ * 128];                // cos/sin table
static __device__ __nv_bfloat16 g_Ahi[(size_t)BATCH * SEQ * D_MODEL];
static __device__ __nv_bfloat16 g_Alo[(size_t)BATCH * SEQ * D_MODEL];
static __device__ __nv_bfloat16 g_Wqkv_hi[(size_t)3 * D_MODEL * D_MODEL]; // [N][K]
static __device__ __nv_bfloat16 g_Wqkv_lo[(size_t)3 * D_MODEL * D_MODEL];
static __device__ __nv_bfloat16 g_Wproj_hi[(size_t)D_MODEL * D_MODEL];
static __device__ __nv_bfloat16 g_Wproj_lo[(size_t)D_MODEL * D_MODEL];
// head-major prepped attention operands: [b][h][t][d]
static __device__ __nv_bfloat16 g_Qhi[(size_t)BATCH * SEQ * D_MODEL];
static __device__ __nv_bfloat16 g_Qlo[(size_t)BATCH * SEQ * D_MODEL];
static __device__ __nv_bfloat16 g_Khi[(size_t)BATCH * SEQ * D_MODEL];
static __device__ __nv_bfloat16 g_Klo[(size_t)BATCH * SEQ * D_MODEL];
static __device__ __nv_bfloat16 g_Vhi[(size_t)BATCH * SEQ * D_MODEL];
static __device__ __nv_bfloat16 g_Vlo[(size_t)BATCH * SEQ * D_MODEL];

// ---------------------------------------------------------------------------
// PTX helpers (sm_80+ subset: cp.async / ldmatrix / mma.sync)
// ---------------------------------------------------------------------------
__device__ __forceinline__ uint32_t smem_to_u32(const void* smem_ptr) {
    uint32_t addr;
    asm("{ .reg .u64 tmp; cvta.to.shared.u64 tmp, %1; cvt.u32.u64 %0, tmp; }"
        : "=r"(addr) : "l"(smem_ptr));
    return addr;
}

__device__ __forceinline__ void cp_async16(uint32_t smem_dst, const void* gmem_src) {
    asm volatile("cp.async.cg.shared.global.L2::128B [%0], [%1], 16;"
                 :: "r"(smem_dst), "l"(__cvta_generic_to_global(gmem_src)));
}
#define CP_ASYNC_COMMIT() asm volatile("cp.async.commit_group;" ::: "memory")
#define CP_ASYNC_WAIT_1() asm volatile("cp.async.wait_group 1;" ::: "memory")
#define CP_ASYNC_WAIT_2() asm volatile("cp.async.wait_group 2;" ::: "memory")

__device__ __forceinline__ void ldsm4(uint32_t* r, uint32_t addr) {
    asm volatile("ldmatrix.sync.aligned.m8n8.x4.shared.b16 {%0,%1,%2,%3}, [%4];"
                 : "=r"(r[0]), "=r"(r[1]), "=r"(r[2]), "=r"(r[3]) : "r"(addr));
}
__device__ __forceinline__ void ldsm4t(uint32_t* r, uint32_t addr) {
    asm volatile("ldmatrix.sync.aligned.m8n8.x4.trans.shared.b16 {%0,%1,%2,%3}, [%4];"
                 : "=r"(r[0]), "=r"(r[1]), "=r"(r[2]), "=r"(r[3]) : "r"(addr));
}

__device__ __forceinline__ void mma_bf16(float* c, const uint32_t* a,
                                         uint32_t b0, uint32_t b1) {
    asm volatile(
        "mma.sync.aligned.m16n8k16.row.col.f32.bf16.bf16.f32 "
        "{%0,%1,%2,%3}, {%4,%5,%6,%7}, {%8,%9}, {%0,%1,%2,%3};"
        : "+f"(c[0]), "+f"(c[1]), "+f"(c[2]), "+f"(c[3])
        : "r"(a[0]), "r"(a[1]), "r"(a[2]), "r"(a[3]), "r"(b0), "r"(b1));
}

// pack (s0 -> low bf16, s1 -> high bf16) into hi; residuals into lo.
__device__ __forceinline__ void split2(float s0, float s1, uint32_t& hi, uint32_t& lo) {
    asm("cvt.rn.bf16x2.f32 %0, %1, %2;" : "=r"(hi) : "f"(s1), "f"(s0));
    __nv_bfloat162 hv = *reinterpret_cast<__nv_bfloat162*>(&hi);
    float r0 = s0 - __bfloat162float(hv.x);
    float r1 = s1 - __bfloat162float(hv.y);
    asm("cvt.rn.bf16x2.f32 %0, %1, %2;" : "=r"(lo) : "f"(r1), "f"(r0));
}

// ---------------------------------------------------------------------------
// RoPE table
// ---------------------------------------------------------------------------
__global__ void rope_table_kernel()
{
    const float RATE_C = 0.14391156831212787f; // ln(10000)/64
    int i = blockIdx.x * blockDim.x + threadIdx.x;  // t*64 + j
    int t = i >> 6, j = i & 63;
    float rate = expf(-RATE_C * (float)j);
    float sv, cv;
    sincosf((float)t * rate, &sv, &cv);
    g_rope[t * 128 + j]      = cv;
    g_rope[t * 128 + 64 + j] = sv;
}

// ---------------------------------------------------------------------------
// Elementwise split: fp32 -> (hi, lo) bf16 pair.
// ---------------------------------------------------------------------------
__global__ void split_kernel(const float* __restrict__ X,
                             __nv_bfloat16* __restrict__ hi,
                             __nv_bfloat16* __restrict__ lo, int n4)
{
    int i = blockIdx.x * blockDim.x + threadIdx.x;
    if (i >= n4) return;
    float4 v = *(const float4*)(X + (size_t)i * 4);
    __nv_bfloat16 h[4], l[4];
    float vv[4] = {v.x, v.y, v.z, v.w};
#pragma unroll
    for (int j = 0; j < 4; ++j) {
        h[j] = __float2bfloat16(vv[j]);
        l[j] = __float2bfloat16(vv[j] - __bfloat162float(h[j]));
    }
    *(uint2*)(hi + (size_t)i * 4) = *(uint2*)h;
    *(uint2*)(lo + (size_t)i * 4) = *(uint2*)l;
}

// ---------------------------------------------------------------------------
// Transpose + split: W[K,N] fp32 -> Thi/Tlo [N,K] bf16 (K-major for MMA B).
// ---------------------------------------------------------------------------
__global__ __launch_bounds__(256) void transpose_split_kernel(
    const float* __restrict__ W,
    __nv_bfloat16* __restrict__ Thi, __nv_bfloat16* __restrict__ Tlo,
    int K, int N)
{
    __shared__ float tile[64][65];
    const int k0 = blockIdx.y * 64;
    const int n0 = blockIdx.x * 64;
    const int tid = threadIdx.x;

#pragma unroll
    for (int j = 0; j < 4; ++j) {
        int idx = tid + j * 256;
        int r  = idx >> 4;
        int c4 = (idx & 15) * 4;
        float4 v = *(const float4*)(W + (size_t)(k0 + r) * N + n0 + c4);
        tile[r][c4 + 0] = v.x; tile[r][c4 + 1] = v.y;
        tile[r][c4 + 2] = v.z; tile[r][c4 + 3] = v.w;
    }
    __syncthreads();

    const int n  = tid >> 2;
    const int ks = (tid & 3) * 16;
    __nv_bfloat16 h[16], l[16];
#pragma unroll
    for (int j = 0; j < 16; ++j) {
        float v = tile[ks + j][n];
        h[j] = __float2bfloat16(v);
        l[j] = __float2bfloat16(v - __bfloat162float(h[j]));
    }
    size_t base = (size_t)(n0 + n) * K + k0 + ks;
    *(uint4*)(Thi + base)     = ((uint4*)h)[0];
    *(uint4*)(Thi + base + 8) = ((uint4*)h)[1];
    *(uint4*)(Tlo + base)     = ((uint4*)l)[0];
    *(uint4*)(Tlo + base + 8) = ((uint4*)l)[1];
}

// ---------------------------------------------------------------------------
// bf16x3 HMMA GEMM (unchanged from R9): 4 warps 2x2, 64x64 warp tiles,
// 3-stage XOR-swizzled cp.async pipeline, 1 barrier/iter, 2 CTAs/SM.
// ---------------------------------------------------------------------------
#define GB_OP     (128 * 64)                // 8192 B per operand tile
#define GB_STAGE  (4 * GB_OP)               // 32768 B
#define GB_NSTAGE 3
#define GB_SMEM   (GB_NSTAGE * GB_STAGE)    // 98304 B (>= 128*132*4 = 67584)

#define GB_SWIZ(row, c) ((uint32_t)((row) * 64 + (((c) ^ (((row) >> 1) & 3)) * 16)))

__device__ __forceinline__ void gemm_load_stage(
    uint32_t st,
    const __nv_bfloat16* __restrict__ Ahi, const __nv_bfloat16* __restrict__ Alo,
    const __nv_bfloat16* __restrict__ Bhi, const __nv_bfloat16* __restrict__ Blo,
    int bm, int bn, int k0, int K, int tid)
{
#pragma unroll
    for (int j = 0; j < 4; ++j) {
        int idx = tid + j * 128;            // 0..511
        int row = idx >> 2;                 // 0..127
        int c   = idx & 3;                  // 16B chunk within 64B row
        uint32_t off = GB_SWIZ(row, c);
        size_t ga = (size_t)(bm + row) * K + k0 + c * 8;
        size_t gb = (size_t)(bn + row) * K + k0 + c * 8;
        cp_async16(st + off,              Ahi + ga);
        cp_async16(st + GB_OP + off,      Alo + ga);
        cp_async16(st + 2 * GB_OP + off,  Bhi + gb);
        cp_async16(st + 3 * GB_OP + off,  Blo + gb);
    }
}

__global__ __launch_bounds__(128, 2) void gemm_bf16x3_kernel(
    const __nv_bfloat16* __restrict__ Ahi, const __nv_bfloat16* __restrict__ Alo,
    const __nv_bfloat16* __restrict__ Bhi, const __nv_bfloat16* __restrict__ Blo,
    const float* __restrict__ bias, float* __restrict__ C,
    int M, int N, int K, int fuse_qkv)
{
    extern __shared__ __align__(128) char smem[];
    const uint32_t sbase = smem_to_u32(smem);
    const int tid  = threadIdx.x;
    const int lane = tid & 31;
    const int wid  = tid >> 5;              // 0..3
    const int wm   = wid >> 1;              // 0..1 (64-row stripes)
    const int wn   = wid & 1;               // 0..1 (64-col stripes)
    const int bm   = blockIdx.y * 128;
    const int bn   = blockIdx.x * 128;

    float acc[4][8][4];
#pragma unroll
    for (int mi = 0; mi < 4; ++mi)
#pragma unroll
        for (int ni = 0; ni < 8; ++ni)
#pragma unroll
            for (int r = 0; r < 4; ++r) acc[mi][ni][r] = 0.f;

    const int nk = K / 32;

    gemm_load_stage(sbase,            Ahi, Alo, Bhi, Blo, bm, bn, 0,  K, tid);
    CP_ASYNC_COMMIT();
    gemm_load_stage(sbase + GB_STAGE, Ahi, Alo, Bhi, Blo, bm, bn, 32, K, tid);
    CP_ASYNC_COMMIT();

    const int lrowA = lane & 15, lcolA = lane >> 4;
    const int bg    = lane >> 3, blr  = lane & 7;

    for (int i = 0; i < nk; ++i) {
        const uint32_t st = sbase + (uint32_t)(i % GB_NSTAGE) * GB_STAGE;
        CP_ASYNC_WAIT_1();
        __syncthreads();

        if (i + 2 < nk) {
            gemm_load_stage(sbase + (uint32_t)((i + 2) % GB_NSTAGE) * GB_STAGE,
                            Ahi, Alo, Bhi, Blo, bm, bn, (i + 2) * 32, K, tid);
        }
        CP_ASYNC_COMMIT();

        const uint32_t aHi = st;
        const uint32_t aLo = st + GB_OP;
        const uint32_t bHi = st + 2 * GB_OP;
        const uint32_t bLo = st + 3 * GB_OP;

#pragma unroll
        for (int ks = 0; ks < 2; ++ks) {
            uint32_t ah[4][4], al[4][4];
#pragma unroll
            for (int mi = 0; mi < 4; ++mi) {
                int row = wm * 64 + mi * 16 + lrowA;
                uint32_t off = GB_SWIZ(row, ks * 2 + lcolA);
                ldsm4(ah[mi], aHi + off);
                ldsm4(al[mi], aLo + off);
            }
#pragma unroll
            for (int np = 0; np < 4; ++np) {
                uint32_t bh[4], bl[4];
                int row = wn * 64 + np * 16 + (bg >> 1) * 8 + blr;
                uint32_t off = GB_SWIZ(row, ks * 2 + (bg & 1));
                ldsm4(bh, bHi + off);
                ldsm4(bl, bLo + off);
#pragma unroll
                for (int mi = 0; mi < 4; ++mi)
#pragma unroll
                    for (int q = 0; q < 2; ++q) {
                        int ni = np * 2 + q, pr = q * 2;
                        mma_bf16(acc[mi][ni], ah[mi], bh[pr], bh[pr + 1]);
                        mma_bf16(acc[mi][ni], ah[mi], bl[pr], bl[pr + 1]);
                        mma_bf16(acc[mi][ni], al[mi], bh[pr], bh[pr + 1]);
                    }
            }
        }
    }

    const int gid = lane >> 2, tig = lane & 3;

    if (fuse_qkv == 0) {
#pragma unroll
        for (int mi = 0; mi < 4; ++mi)
#pragma unroll
            for (int ni = 0; ni < 8; ++ni) {
                int row = bm + wm * 64 + mi * 16 + gid;
                int col = bn + wn * 64 + ni * 8 + tig * 2;
                float2 bv = *(const float2*)(bias + col);
                float2 v0 = make_float2(acc[mi][ni][0] + bv.x, acc[mi][ni][1] + bv.y);
                float2 v1 = make_float2(acc[mi][ni][2] + bv.x, acc[mi][ni][3] + bv.y);
                *(float2*)(C + (size_t)row * N + col)       = v0;
                *(float2*)(C + (size_t)(row + 8) * N + col) = v1;
            }
        return;
    }

    // ---- fused QKV epilogue: rope/scale/split, head-major bf16 hi/lo ----
    __syncthreads();
    float* Cs = (float*)smem;                 // 128 x 132 fp32, reuses stages
#pragma unroll
    for (int mi = 0; mi < 4; ++mi)
#pragma unroll
        for (int ni = 0; ni < 8; ++ni) {
            int row = wm * 64 + mi * 16 + gid;
            int col = wn * 64 + ni * 8 + tig * 2;
            float2 bv = *(const float2*)(bias + bn + col);
            Cs[row * 132 + col]           = acc[mi][ni][0] + bv.x;
            Cs[row * 132 + col + 1]       = acc[mi][ni][1] + bv.y;
            Cs[(row + 8) * 132 + col]     = acc[mi][ni][2] + bv.x;
            Cs[(row + 8) * 132 + col + 1] = acc[mi][ni][3] + bv.y;
        }
    __syncthreads();

    const int sel = bn >> 11;                 // 0=Q, 1=K, 2=V
    const int hh  = (bn & 2047) >> 7;         // head
    __nv_bfloat16 *dh, *dl;
    if (sel == 0)      { dh = g_Qhi; dl = g_Qlo; }
    else if (sel == 1) { dh = g_Khi; dl = g_Klo; }
    else               { dh = g_Vhi; dl = g_Vlo; }
    const float SCALE = 0.08838834764831845f; // 1/sqrt(128)

    for (int i = tid; i < 128 * 32; i += 128) {
        int row = i >> 5, jp = (i & 31) * 2;
        int tg = bm + row, t = tg & (SEQ - 1), bb = tg >> 11;
        float x1a = Cs[row * 132 + jp],      x1b = Cs[row * 132 + jp + 1];
        float x2a = Cs[row * 132 + jp + 64], x2b = Cs[row * 132 + jp + 65];
        float y1a, y1b, y2a, y2b;
        if (sel < 2) {
            float cva = g_rope[t * 128 + jp],     sva = g_rope[t * 128 + 64 + jp];
            float cvb = g_rope[t * 128 + jp + 1], svb = g_rope[t * 128 + 64 + jp + 1];
            y1a = x1a * cva - x2a * sva;  y2a = x1a * sva + x2a * cva;
            y1b = x1b * cvb - x2b * svb;  y2b = x1b * svb + x2b * cvb;
            if (sel == 0) { y1a *= SCALE; y2a *= SCALE; y1b *= SCALE; y2b *= SCALE; }
        } else {
            y1a = x1a; y1b = x1b; y2a = x2a; y2b = x2b;
        }
        size_t base = ((size_t)(bb * N_HEAD + hh) * SEQ + t) * HEAD_DIM;
        uint32_t hi, lo;
        split2(y1a, y1b, hi, lo);
        *(uint32_t*)(dh + base + jp)      = hi;
        *(uint32_t*)(dl + base + jp)      = lo;
        split2(y2a, y2b, hi, lo);
        *(uint32_t*)(dh + base + jp + 64) = hi;
        *(uint32_t*)(dl + base + jp + 64) = lo;
    }
}

// ---------------------------------------------------------------------------
// MMA flash attention, R10: Q hoisted to REGISTERS, Q smem reused as third KV
// buffer -> 3-stage KV pipeline, ONE __syncthreads per K-tile, prefetch
// issued before MMA (overlaps full compute phase).
// ---------------------------------------------------------------------------
#define FA_TQ 128
#define FA_TK 64
#define FA_ROWB 272
#define FA_BUF  69632                 // KV buffer: KHI +0, KLO +17408, VHI +34816, VLO +52224
#define FA_SMEM (3 * FA_BUF)          // 208896; Q staged in buf2 then recycled

__device__ __forceinline__ void fa_load_kv(uint32_t buf, size_t bh_elem, int k0, int tid)
{
    size_t gbase = bh_elem + (size_t)k0 * HEAD_DIM;
    for (int i = tid; i < FA_TK * 16; i += 256) {
        int row = i >> 4, c = i & 15;
        uint32_t soff = (uint32_t)(row * FA_ROWB + c * 16);
        size_t   goff = gbase + (size_t)row * HEAD_DIM + c * 8;
        cp_async16(buf + soff,         g_Khi + goff);
        cp_async16(buf + 17408 + soff, g_Klo + goff);
        cp_async16(buf + 34816 + soff, g_Vhi + goff);
        cp_async16(buf + 52224 + soff, g_Vlo + goff);
    }
}

__global__ __launch_bounds__(256, 1) void flash_attn_mma_kernel()
{
    extern __shared__ __align__(128) char sm[];
    const uint32_t sbase = smem_to_u32(sm);

    const int tid  = threadIdx.x;
    const int lane = tid & 31;
    const int wid  = tid >> 5;
    const int qt   = (gridDim.x - 1) - blockIdx.x;   // heavy tiles first
    const int q0   = qt * FA_TQ;
    const int b    = blockIdx.y >> 4;
    const int h    = blockIdx.y & 15;

    const size_t bh_elem = (size_t)(b * N_HEAD + h) * SEQ * HEAD_DIM;
    const int ktmax = 2 * qt + 1;                    // >= 1 always

    // ---- prologue loads: Q -> buf2 region (group 0), KV0 (g1), KV1 (g2) ----
    {
        size_t qbase = bh_elem + (size_t)q0 * HEAD_DIM;
        const uint32_t qarea = sbase + 2 * FA_BUF;   // QHI +0 (128*272), QLO +34816
        for (int i = tid; i < FA_TQ * 16; i += 256) {
            int row = i >> 4, c = i & 15;
            uint32_t soff = (uint32_t)(row * FA_ROWB + c * 16);
            size_t   goff = qbase + (size_t)row * HEAD_DIM + c * 8;
            cp_async16(qarea + soff,         g_Qhi + goff);
            cp_async16(qarea + 34816 + soff, g_Qlo + goff);
        }
    }
    CP_ASYNC_COMMIT();                               // g0: Q
    fa_load_kv(sbase, bh_elem, 0, tid);
    CP_ASYNC_COMMIT();                               // g1: KV0
    fa_load_kv(sbase + FA_BUF, bh_elem, FA_TK, tid);
    CP_ASYNC_COMMIT();                               // g2: KV1

    const int gid = lane >> 2, tig = lane & 3;
    const int lrowA = lane & 15, lcolA = lane >> 4;
    const int bg = lane >> 3, blr = lane & 7;
    const int wrow_lo = q0 + wid * 16;

    // ---- hoist Q into registers (then buf2 is recycled as KV buffer) ----
    uint32_t qh[8][4], ql[8][4];
    CP_ASYNC_WAIT_2();              // g0 (Q) complete
    __syncthreads();
    {
        const uint32_t qarea = sbase + 2 * FA_BUF;
#pragma unroll
        for (int ks = 0; ks < 8; ++ks) {
            uint32_t qoff = (uint32_t)((wid * 16 + lrowA) * FA_ROWB
                                       + (ks * 16 + lcolA * 8) * 2);
            ldsm4(qh[ks], qarea + qoff);
            ldsm4(ql[ks], qarea + 34816 + qoff);
        }
    }
    __syncthreads();                // Q reads done -> buf2 free for KV2

    float oacc[16][4];
#pragma unroll
    for (int ni = 0; ni < 16; ++ni)
#pragma unroll
        for (int r = 0; r < 4; ++r) oacc[ni][r] = 0.f;
    float m0 = -1e30f, m1 = -1e30f, l0 = 0.f, l1 = 0.f;

    for (int kt = 0; kt <= ktmax; ++kt) {
        const int k0 = kt * FA_TK;
        const uint32_t buf = sbase + (uint32_t)(kt % 3) * FA_BUF;
        CP_ASYNC_WAIT_1();          // KV[kt] resident; KV[kt+1] may pend
        __syncthreads();            // data visible + prior-iter buffer reads done

        // prefetch KV[kt+2] into buf (kt+2)%3 (consumed at iter kt-1) -> overlaps MMA
        if (kt + 2 <= ktmax)
            fa_load_kv(sbase + (uint32_t)((kt + 2) % 3) * FA_BUF,
                       bh_elem, (kt + 2) * FA_TK, tid);
        CP_ASYNC_COMMIT();

        if (k0 <= wrow_lo + 15) {   // warp-level causal skip
            // ---- S = Q(regs) @ K^T, bf16x3 ----
            float sacc[8][4];
#pragma unroll
            for (int ni = 0; ni < 8; ++ni)
#pragma unroll
                for (int r = 0; r < 4; ++r) sacc[ni][r] = 0.f;

#pragma unroll
            for (int ks = 0; ks < 8; ++ks) {
#pragma unroll
                for (int np = 0; np < 4; ++np) {
                    uint32_t kh[4], kl[4];
                    uint32_t koff = (uint32_t)((np * 16 + (bg >> 1) * 8 + blr) * FA_ROWB
                                               + (ks * 16 + (bg & 1) * 8) * 2);
                    ldsm4(kh, buf + koff);
                    ldsm4(kl, buf + 17408 + koff);
#pragma unroll
                    for (int q = 0; q < 2; ++q) {
                        int ni = np * 2 + q, pr = q * 2;
                        mma_bf16(sacc[ni], qh[ks], kh[pr], kh[pr + 1]);
                        mma_bf16(sacc[ni], qh[ks], kl[pr], kl[pr + 1]);
                        mma_bf16(sacc[ni], ql[ks], kh[pr], kh[pr + 1]);
                    }
                }
            }

            // ---- causal mask (partial tiles only) ----
            const int row0 = wrow_lo + gid, row1 = row0 + 8;
            if (k0 + FA_TK - 1 > q0) {
#pragma unroll
                for (int ni = 0; ni < 8; ++ni) {
                    int col = k0 + ni * 8 + tig * 2;
                    if (col     > row0) sacc[ni][0] = -1e30f;
                    if (col + 1 > row0) sacc[ni][1] = -1e30f;
                    if (col     > row1) sacc[ni][2] = -1e30f;
                    if (col + 1 > row1) sacc[ni][3] = -1e30f;
                }
            }

            // ---- online softmax ----
            float mx0 = -1e30f, mx1 = -1e30f;
#pragma unroll
            for (int ni = 0; ni < 8; ++ni) {
                mx0 = fmaxf(mx0, fmaxf(sacc[ni][0], sacc[ni][1]));
                mx1 = fmaxf(mx1, fmaxf(sacc[ni][2], sacc[ni][3]));
            }
#pragma unroll
            for (int off = 1; off < 4; off <<= 1) {
                mx0 = fmaxf(mx0, __shfl_xor_sync(0xffffffffu, mx0, off));
                mx1 = fmaxf(mx1, __shfl_xor_sync(0xffffffffu, mx1, off));
            }
            float mn0 = fmaxf(m0, mx0), mn1 = fmaxf(m1, mx1);
            float a0 = __expf(m0 - mn0), a1 = __expf(m1 - mn1);
            m0 = mn0; m1 = mn1;
            float sum0 = 0.f, sum1 = 0.f;
#pragma unroll
            for (int ni = 0; ni < 8; ++ni) {
                sacc[ni][0] = __expf(sacc[ni][0] - mn0);
                sacc[ni][1] = __expf(sacc[ni][1] - mn0);
                sacc[ni][2] = __expf(sacc[ni][2] - mn1);
                sacc[ni][3] = __expf(sacc[ni][3] - mn1);
                sum0 += sacc[ni][0] + sacc[ni][1];
                sum1 += sacc[ni][2] + sacc[ni][3];
            }
#pragma unroll
            for (int off = 1; off < 4; off <<= 1) {
                sum0 += __shfl_xor_sync(0xffffffffu, sum0, off);
                sum1 += __shfl_xor_sync(0xffffffffu, sum1, off);
            }
            l0 = l0 * a0 + sum0;
            l1 = l1 * a1 + sum1;
#pragma unroll
            for (int ni = 0; ni < 16; ++ni) {
                oacc[ni][0] *= a0; oacc[ni][1] *= a0;
                oacc[ni][2] *= a1; oacc[ni][3] *= a1;
            }

            // ---- O += P @ V, bf16x3 (V via trans ldmatrix) ----
            const uint32_t vhi = buf + 34816, vlo = buf + 52224;
#pragma unroll
            for (int kc = 0; kc < 4; ++kc) {
                uint32_t ah[4], al[4];
                split2(sacc[2 * kc][0],     sacc[2 * kc][1],     ah[0], al[0]);
                split2(sacc[2 * kc][2],     sacc[2 * kc][3],     ah[1], al[1]);
                split2(sacc[2 * kc + 1][0], sacc[2 * kc + 1][1], ah[2], al[2]);
                split2(sacc[2 * kc + 1][2], sacc[2 * kc + 1][3], ah[3], al[3]);
#pragma unroll
                for (int np = 0; np < 8; ++np) {
                    uint32_t vh[4], vl[4];
                    uint32_t voff = (uint32_t)((kc * 16 + (lane & 15)) * FA_ROWB
                                               + (np * 16 + (lane >> 4) * 8) * 2);
                    ldsm4t(vh, vhi + voff);
                    ldsm4t(vl, vlo + voff);
#pragma unroll
                    for (int q = 0; q < 2; ++q) {
                        int ni = np * 2 + q, pr = q * 2;
                        mma_bf16(oacc[ni], ah, vh[pr], vh[pr + 1]);
                        mma_bf16(oacc[ni], ah, vl[pr], vl[pr + 1]);
                        mma_bf16(oacc[ni], al, vh[pr], vh[pr + 1]);
                    }
                }
            }
        }
    }

    // ---- epilogue: normalize, split to bf16 hi/lo, store ----
    {
        float inv0 = 1.f / l0, inv1 = 1.f / l1;
        int t0 = wrow_lo + gid;
        size_t base0 = (size_t)(b * SEQ + t0) * D_MODEL + h * HEAD_DIM;
        size_t base1 = (size_t)(b * SEQ + t0 + 8) * D_MODEL + h * HEAD_DIM;
#pragma unroll
        for (int ni = 0; ni < 16; ++ni) {
            int col = ni * 8 + tig * 2;
            uint32_t hi, lo;
            split2(oacc[ni][0] * inv0, oacc[ni][1] * inv0, hi, lo);
            *(uint32_t*)(g_Ahi + base0 + col) = hi;
            *(uint32_t*)(g_Alo + base0 + col) = lo;
            split2(oacc[ni][2] * inv1, oacc[ni][3] * inv1, hi, lo);
            *(uint32_t*)(g_Ahi + base1 + col) = hi;
            *(uint32_t*)(g_Alo + base1 + col) = lo;
        }
    }
}

// ---------------------------------------------------------------------------
extern "C" void kernel_launch(void* const* d_in, const int* in_sizes, int n_in,
                              void* d_out, int out_size)
{
    (void)in_sizes; (void)n_in; (void)out_size;
    const float* x     = (const float*)d_in[0];
    const float* Wqkv  = (const float*)d_in[2];
    const float* bqkv  = (const float*)d_in[3];
    const float* Wproj = (const float*)d_in[4];
    const float* bproj = (const float*)d_in[5];
    float* out = (float*)d_out;

    void *ahi_p, *alo_p, *wq_hi_p, *wq_lo_p, *wp_hi_p, *wp_lo_p;
    cudaGetSymbolAddress(&ahi_p, g_Ahi);
    cudaGetSymbolAddress(&alo_p, g_Alo);
    cudaGetSymbolAddress(&wq_hi_p, g_Wqkv_hi);
    cudaGetSymbolAddress(&wq_lo_p, g_Wqkv_lo);
    cudaGetSymbolAddress(&wp_hi_p, g_Wproj_hi);
    cudaGetSymbolAddress(&wp_lo_p, g_Wproj_lo);
    __nv_bfloat16* Ahi = (__nv_bfloat16*)ahi_p;
    __nv_bfloat16* Alo = (__nv_bfloat16*)alo_p;
    __nv_bfloat16* WqH = (__nv_bfloat16*)wq_hi_p;
    __nv_bfloat16* WqL = (__nv_bfloat16*)wq_lo_p;
    __nv_bfloat16* WpH = (__nv_bfloat16*)wp_hi_p;
    __nv_bfloat16* WpL = (__nv_bfloat16*)wp_lo_p;

    cudaFuncSetAttribute(gemm_bf16x3_kernel,
                         cudaFuncAttributeMaxDynamicSharedMemorySize, GB_SMEM);
    cudaFuncSetAttribute(flash_attn_mma_kernel,
                         cudaFuncAttributeMaxDynamicSharedMemorySize, FA_SMEM);

    const int M = BATCH * SEQ;               // 4096
    const int nelem = M * D_MODEL;

    // 0) RoPE cos/sin table
    rope_table_kernel<<<SEQ * 64 / 256, 256>>>();

    // 1) split activations x -> (Ahi, Alo)
    split_kernel<<<(nelem / 4 + 255) / 256, 256>>>(x, Ahi, Alo, nelem / 4);

    // 2) weight transpose + split
    transpose_split_kernel<<<dim3(3 * D_MODEL / 64, D_MODEL / 64), 256>>>(
        Wqkv, WqH, WqL, D_MODEL, 3 * D_MODEL);
    transpose_split_kernel<<<dim3(D_MODEL / 64, D_MODEL / 64), 256>>>(
        Wproj, WpH, WpL, D_MODEL, D_MODEL);

    // 3) QKV projection with FUSED rope/split epilogue (3-stage, 1 sync/iter)
    gemm_bf16x3_kernel<<<dim3(3 * D_MODEL / 128, M / 128), 128, GB_SMEM>>>(
        Ahi, Alo, WqH, WqL, bqkv, nullptr, M, 3 * D_MODEL, D_MODEL, 1);

    // 4) MMA flash attention: Q in regs, tri-buffered KV, 1 sync/iter
    flash_attn_mma_kernel<<<dim3(SEQ / FA_TQ, BATCH * N_HEAD), 256, FA_SMEM>>>();

    // 5) output projection (plain epilogue)
    gemm_bf16x3_kernel<<<dim3(D_MODEL / 128, M / 128), 128, GB_SMEM>>>(
        Ahi, Alo, WpH, WpL, bproj, out, M, D_MODEL, D_MODEL, 0);
}